// round 8
// baseline (speedup 1.0000x reference)
#include <cuda_runtime.h>
#include <cuda_bf16.h>
#include <cstdint>

#define N_NODES   100000
#define DIM       128
#define NEG       5
#define LR        0.025f
#define NCE_BIAS      11.512925464970229f   // log(100000)
#define NCE_NEG_BIAS  9.9034875525361272f   // log(100000/5)
#define LUT_SIZE  1202

// bf16 gather table. Phase 1 (pos): bf16(original W). Phase 2 (neg):
// rewritten to bf16(post-positive table) by snapshot_kernel.
__device__ __nv_bfloat16 g_snap[(size_t)N_NODES * DIM];

// ---------------------------------------------------------------------------
// helpers
// ---------------------------------------------------------------------------
__device__ __forceinline__ void red4(float* addr, float x, float y, float z, float w) {
    asm volatile("red.global.add.v4.f32 [%0], {%1, %2, %3, %4};"
                 :: "l"(addr), "f"(x), "f"(y), "f"(z), "f"(w)
                 : "memory");
}

__device__ __forceinline__ float lut_sigmoid_sh(float s, const float* lut_sh) {
    s = fminf(fmaxf(s, -6.0f), 6.0f);
    int idx = __float2int_rd((s + 6.01f) * 100.0f);
    idx = max(0, min(idx, LUT_SIZE - 1));
    return lut_sh[idx];
}

__device__ __forceinline__ void unpack4(uint2 r, float f[4]) {
    float2 lo = __bfloat1622float2(*reinterpret_cast<__nv_bfloat162*>(&r.x));
    float2 hi = __bfloat1622float2(*reinterpret_cast<__nv_bfloat162*>(&r.y));
    f[0] = lo.x; f[1] = lo.y; f[2] = hi.x; f[3] = hi.y;
}

__device__ __forceinline__ uint4 pack8(float4 a, float4 b) {
    __nv_bfloat162 p0 = __floats2bfloat162_rn(a.x, a.y);
    __nv_bfloat162 p1 = __floats2bfloat162_rn(a.z, a.w);
    __nv_bfloat162 p2 = __floats2bfloat162_rn(b.x, b.y);
    __nv_bfloat162 p3 = __floats2bfloat162_rn(b.z, b.w);
    uint4 o;
    o.x = *reinterpret_cast<uint32_t*>(&p0);
    o.y = *reinterpret_cast<uint32_t*>(&p1);
    o.z = *reinterpret_cast<uint32_t*>(&p2);
    o.w = *reinterpret_cast<uint32_t*>(&p3);
    return o;
}

__device__ __forceinline__ float4 ldcs4(const float4* p) {
    float4 v;
    asm volatile("ld.global.cs.v4.f32 {%0,%1,%2,%3}, [%4];"
                 : "=f"(v.x), "=f"(v.y), "=f"(v.z), "=f"(v.w) : "l"(p));
    return v;
}

// ---------------------------------------------------------------------------
// K0: out = W (fp32, streaming read) + g_snap = bf16(W).
// Grid-stride, 16 floats per iteration, 4 independent loads in flight.
// ---------------------------------------------------------------------------
__global__ void __launch_bounds__(256)
init_kernel(const float4* __restrict__ W, float4* __restrict__ out, int n16) {
    int stride = gridDim.x * blockDim.x;
    for (int i = blockIdx.x * blockDim.x + threadIdx.x; i < n16; i += stride) {
        float4 a = ldcs4(W + 4 * i);
        float4 b = ldcs4(W + 4 * i + 1);
        float4 c = ldcs4(W + 4 * i + 2);
        float4 d = ldcs4(W + 4 * i + 3);
        out[4 * i]     = a;
        out[4 * i + 1] = b;
        out[4 * i + 2] = c;
        out[4 * i + 3] = d;
        reinterpret_cast<uint4*>(g_snap)[2 * i]     = pack8(a, b);
        reinterpret_cast<uint4*>(g_snap)[2 * i + 1] = pack8(c, d);
    }
}

// K2: g_snap = bf16(out) (post-positive table)
__global__ void __launch_bounds__(256)
snapshot_kernel(const float4* __restrict__ src, int n16) {
    int stride = gridDim.x * blockDim.x;
    for (int i = blockIdx.x * blockDim.x + threadIdx.x; i < n16; i += stride) {
        float4 a = __ldg(src + 4 * i);
        float4 b = __ldg(src + 4 * i + 1);
        float4 c = __ldg(src + 4 * i + 2);
        float4 d = __ldg(src + 4 * i + 3);
        reinterpret_cast<uint4*>(g_snap)[2 * i]     = pack8(a, b);
        reinterpret_cast<uint4*>(g_snap)[2 * i + 1] = pack8(c, d);
    }
}

// ---------------------------------------------------------------------------
// K1: positives. One warp per pair; gathers bf16(W); red4 -> out.
// ---------------------------------------------------------------------------
__global__ void __launch_bounds__(256, 8)
pos_kernel(const float* __restrict__ lut,
           const int*   __restrict__ iu,
           const int*   __restrict__ iv,
           float*       __restrict__ out,
           int n_pairs) {
    __shared__ float lut_sh[LUT_SIZE];
    for (int t = threadIdx.x; t < LUT_SIZE; t += blockDim.x)
        lut_sh[t] = __ldg(lut + t);
    __syncthreads();

    int warp = (blockIdx.x * blockDim.x + threadIdx.x) >> 5;
    int lane = threadIdx.x & 31;
    if (warp >= n_pairs) return;

    const uint2* snap = reinterpret_cast<const uint2*>(g_snap);
    int u = __ldg(iu + warp);
    int v = __ldg(iv + warp);
    int ku = u * 32 + lane;       // shared offset: gather = snap+ku, red = out+4*ku
    int kv = v * 32 + lane;

    uint2 ra = __ldg(snap + ku);
    uint2 rb = __ldg(snap + kv);

    float a[4], b[4];
    unpack4(ra, a);
    unpack4(rb, b);

    float p = a[0] * b[0] + a[1] * b[1] + a[2] * b[2] + a[3] * b[3];
#pragma unroll
    for (int o = 16; o; o >>= 1) p += __shfl_xor_sync(0xffffffffu, p, o);

    float sc = (1.0f - lut_sigmoid_sh(p - NCE_BIAS, lut_sh)) * LR;

    red4(out + 4 * ku, sc * b[0], sc * b[1], sc * b[2], sc * b[3]);
    red4(out + 4 * kv, sc * a[0], sc * a[1], sc * a[2], sc * a[3]);
}

// ---------------------------------------------------------------------------
// K3: negatives. One warp per group of NEG sharing one u. u index comes from
// the dense idx_pos_u array (idx_neg_u = repeat(idx_pos_u, NEG)) -> coalesced.
// ---------------------------------------------------------------------------
__global__ void __launch_bounds__(256, 6)
neg_kernel(const float* __restrict__ lut,
           const int*   __restrict__ ipu,   // dense u indices, one per group
           const int*   __restrict__ inv,
           float*       __restrict__ out,
           int n_groups) {
    __shared__ float lut_sh[LUT_SIZE];
    for (int t = threadIdx.x; t < LUT_SIZE; t += blockDim.x)
        lut_sh[t] = __ldg(lut + t);
    __syncthreads();

    int g    = (blockIdx.x * blockDim.x + threadIdx.x) >> 5;
    int lane = threadIdx.x & 31;
    if (g >= n_groups) return;

    const uint2* snap = reinterpret_cast<const uint2*>(g_snap);

    int u = __ldg(ipu + g);                  // coalesced (4B stride)
    int kk[NEG];
#pragma unroll
    for (int j = 0; j < NEG; j++)
        kk[j] = __ldg(inv + g * NEG + j) * 32 + lane;
    int ku = u * 32 + lane;

    // all 6 gathers in flight before any dependent math
    uint2 ru = __ldg(snap + ku);
    uint2 rb[NEG];
#pragma unroll
    for (int j = 0; j < NEG; j++) rb[j] = __ldg(snap + kk[j]);

    float a[4];
    unpack4(ru, a);

    float p[NEG];
#pragma unroll
    for (int j = 0; j < NEG; j++) {
        float b[4];
        unpack4(rb[j], b);
        p[j] = a[0] * b[0] + a[1] * b[1] + a[2] * b[2] + a[3] * b[3];
    }

#pragma unroll
    for (int o = 16; o; o >>= 1) {
#pragma unroll
        for (int j = 0; j < NEG; j++)
            p[j] += __shfl_xor_sync(0xffffffffu, p[j], o);
    }

#pragma unroll
    for (int j = 0; j < NEG; j++)
        p[j] = -lut_sigmoid_sh(p[j] - NCE_NEG_BIAS, lut_sh) * LR;  // p[] = sc[]

    float du0 = 0.f, du1 = 0.f, du2 = 0.f, du3 = 0.f;
#pragma unroll
    for (int j = 0; j < NEG; j++) {
        float b[4];
        unpack4(rb[j], b);
        du0 += p[j] * b[0]; du1 += p[j] * b[1];
        du2 += p[j] * b[2]; du3 += p[j] * b[3];
        red4(out + 4 * kk[j],
             p[j] * a[0], p[j] * a[1], p[j] * a[2], p[j] * a[3]);
    }
    red4(out + 4 * ku, du0, du1, du2, du3);
}

// ---------------------------------------------------------------------------
// launch
// ---------------------------------------------------------------------------
extern "C" void kernel_launch(void* const* d_in, const int* in_sizes, int n_in,
                              void* d_out, int out_size) {
    const float* W    = (const float*)d_in[0];
    const float* lut  = (const float*)d_in[1];
    const int*   ipu  = (const int*)d_in[2];
    const int*   ipv  = (const int*)d_in[3];
    const int*   inv  = (const int*)d_in[5];
    float*       out  = (float*)d_out;

    const int n_pos   = in_sizes[2];          // 100000
    const int n_neg   = in_sizes[4];          // 500000
    const int n_group = n_neg / NEG;          // 100000
    const int n16     = out_size / 16;        // 800,000

    const int CT = 256;
    const int copy_blocks = 148 * 8;          // grid-stride, ~waves of full chip

    init_kernel<<<copy_blocks, CT>>>((const float4*)W, (float4*)out, n16);
    pos_kernel<<<(n_pos * 32 + CT - 1) / CT, CT>>>(lut, ipu, ipv, out, n_pos);
    snapshot_kernel<<<copy_blocks, CT>>>((const float4*)out, n16);
    neg_kernel<<<(n_group * 32 + CT - 1) / CT, CT>>>(lut, ipu, inv, out, n_group);
}